// round 12
// baseline (speedup 1.0000x reference)
#include <cuda_runtime.h>
#include <cuda_bf16.h>
#include <math.h>
#include <stdint.h>

#define T_TOK   8192
#define D_MODEL 1024
#define D_FF    4096
#define N_EXP   8
#define EXP_BASE 8192
#define MAX_ROWS 25600
#define NRB (MAX_ROWS / 128)   // 200

// ---------------- device scratch (static) ----------------
__device__ __align__(128) __nv_bfloat16 d_xhi[(size_t)T_TOK * D_MODEL];
__device__ __align__(128) __nv_bfloat16 d_xlo[(size_t)T_TOK * D_MODEL];
__device__ __align__(128) __nv_bfloat16 d_w1hi[(size_t)9 * D_FF * D_MODEL];   // [g][N=4096][K=1024]
__device__ __align__(128) __nv_bfloat16 d_w1lo[(size_t)9 * D_FF * D_MODEL];
__device__ __align__(128) __nv_bfloat16 d_w2hi[(size_t)9 * D_MODEL * D_FF];   // [g][N=1024][K=4096]
__device__ __align__(128) __nv_bfloat16 d_w2lo[(size_t)9 * D_MODEL * D_FF];
__device__ __align__(128) __nv_bfloat16 d_hhi[(size_t)MAX_ROWS * D_FF];
__device__ __align__(128) __nv_bfloat16 d_hlo[(size_t)MAX_ROWS * D_FF];
__device__ __align__(128) float d_y[(size_t)MAX_ROWS * D_MODEL];
__device__ int   d_row_tok[MAX_ROWS];
__device__ int   d_e0[T_TOK], d_e1[T_TOK];
__device__ float d_w0[T_TOK], d_w1v[T_TOK];
__device__ int   d_slot0[T_TOK], d_slot1[T_TOK];
__device__ int   d_counts[N_EXP];
__device__ int   d_fill[N_EXP];
__device__ int   d_est[N_EXP + 1];

// ---------------- helpers ----------------
__device__ __forceinline__ uint32_t smem_u32(const void* p) {
    uint32_t a;
    asm("{ .reg .u64 t; cvta.to.shared.u64 t, %1; cvt.u32.u64 %0, t; }" : "=r"(a) : "l"(p));
    return a;
}
__device__ __forceinline__ void cpa(uint32_t d, const void* s, int sz) {
    asm volatile("cp.async.cg.shared.global [%0], [%1], 16, %2;" :: "r"(d), "l"(s), "r"(sz) : "memory");
}
#define CP_COMMIT() asm volatile("cp.async.commit_group;" ::: "memory")
#define CP_WAIT0()  asm volatile("cp.async.wait_group 0;" ::: "memory")

__device__ __forceinline__ uint4 ldm4(uint32_t a) {
    uint4 r;
    asm volatile("ldmatrix.sync.aligned.m8n8.x4.shared.b16 {%0,%1,%2,%3}, [%4];"
                 : "=r"(r.x), "=r"(r.y), "=r"(r.z), "=r"(r.w) : "r"(a));
    return r;
}
__device__ __forceinline__ void mma16816(float* c, const uint4& a, uint32_t b0, uint32_t b1) {
    asm volatile(
        "mma.sync.aligned.m16n8k16.row.col.f32.bf16.bf16.f32 "
        "{%0,%1,%2,%3},{%4,%5,%6,%7},{%8,%9},{%0,%1,%2,%3};"
        : "+f"(c[0]), "+f"(c[1]), "+f"(c[2]), "+f"(c[3])
        : "r"(a.x), "r"(a.y), "r"(a.z), "r"(a.w), "r"(b0), "r"(b1));
}
__device__ __forceinline__ float gelu_exact(float v) {
    return 0.5f * v * (1.0f + erff(v * 0.70710678118654752440f));
}

// smem stage: A_hi[0,16K) A_lo[16K,32K) B_hi[32K,64K) B_lo[64K,96K); 2 stages
#define STAGE_SZ 98304
#define GEMM_SMEM (2 * STAGE_SZ)   // 192 KB

// ---------------- init / router / offsets / scatter ----------------
__global__ void init_kernel() {
    int i = blockIdx.x * blockDim.x + threadIdx.x;
    if (i < N_EXP) { d_counts[i] = 0; d_fill[i] = 0; }
    if (i < MAX_ROWS) d_row_tok[i] = (i < T_TOK) ? i : -1;
}

__global__ void router_kernel(const float* __restrict__ x,
                              const float* __restrict__ rw,
                              const float* __restrict__ rb) {
    int gid = blockIdx.x * blockDim.x + threadIdx.x;
    int t = gid >> 5, lane = gid & 31;
    if (t >= T_TOK) return;
    const float* xr = x + (size_t)t * D_MODEL;
    float acc[N_EXP];
#pragma unroll
    for (int e = 0; e < N_EXP; e++) acc[e] = 0.0f;
    for (int k = lane; k < D_MODEL; k += 32) {
        float xv = xr[k];
        const float4* w4 = (const float4*)(rw + (size_t)k * N_EXP);
        float4 wa = w4[0], wb = w4[1];
        acc[0] += xv * wa.x; acc[1] += xv * wa.y; acc[2] += xv * wa.z; acc[3] += xv * wa.w;
        acc[4] += xv * wb.x; acc[5] += xv * wb.y; acc[6] += xv * wb.z; acc[7] += xv * wb.w;
    }
#pragma unroll
    for (int off = 16; off > 0; off >>= 1)
#pragma unroll
        for (int e = 0; e < N_EXP; e++) acc[e] += __shfl_xor_sync(0xFFFFFFFFu, acc[e], off);
    if (lane == 0) {
        float l[N_EXP], m = -1e30f;
#pragma unroll
        for (int e = 0; e < N_EXP; e++) { l[e] = acc[e] + rb[e]; m = fmaxf(m, l[e]); }
        float p[N_EXP], s = 0.0f;
#pragma unroll
        for (int e = 0; e < N_EXP; e++) { p[e] = __expf(l[e] - m); s += p[e]; }
        float inv = 1.0f / s;
#pragma unroll
        for (int e = 0; e < N_EXP; e++) p[e] *= inv;
        int i0 = 0; float p0 = p[0];
#pragma unroll
        for (int e = 1; e < N_EXP; e++) if (p[e] > p0) { p0 = p[e]; i0 = e; }
        int i1 = -1; float p1 = -1e30f;
#pragma unroll
        for (int e = 0; e < N_EXP; e++) { if (e == i0) continue; if (p[e] > p1) { p1 = p[e]; i1 = e; } }
        float denom = p0 + p1 + 1e-9f;
        d_e0[t] = i0; d_e1[t] = i1;
        d_w0[t] = p0 / denom; d_w1v[t] = p1 / denom;
        atomicAdd(&d_counts[i0], 1);
        atomicAdd(&d_counts[i1], 1);
    }
}

__global__ void offsets_kernel() {
    if (threadIdx.x == 0 && blockIdx.x == 0) {
        int run = EXP_BASE;
#pragma unroll
        for (int e = 0; e < N_EXP; e++) { d_est[e] = run; run += (d_counts[e] + 127) & ~127; }
        d_est[N_EXP] = run;
    }
}

__global__ void scatter_kernel() {
    int t = blockIdx.x * blockDim.x + threadIdx.x;
    if (t >= T_TOK) return;
    int e0 = d_e0[t];
    int r0 = d_est[e0] + atomicAdd(&d_fill[e0], 1);
    d_row_tok[r0] = t; d_slot0[t] = r0;
    int e1 = d_e1[t];
    int r1 = d_est[e1] + atomicAdd(&d_fill[e1], 1);
    d_row_tok[r1] = t; d_slot1[t] = r1;
}

// ---------------- x split: fp32 -> bf16 hi/lo ----------------
__global__ void split_x_kernel(const float* __restrict__ x) {
    size_t i = ((size_t)blockIdx.x * blockDim.x + threadIdx.x) * 4;
    float4 v = *(const float4*)(x + i);
    union { __nv_bfloat16 h[4]; uint2 u; } hi, lo;
    float f[4] = { v.x, v.y, v.z, v.w };
#pragma unroll
    for (int j = 0; j < 4; j++) {
        __nv_bfloat16 hb = __float2bfloat16(f[j]);
        hi.h[j] = hb;
        lo.h[j] = __float2bfloat16(f[j] - __bfloat162float(hb));
    }
    *(uint2*)(d_xhi + i) = hi.u;
    *(uint2*)(d_xlo + i) = lo.u;
}

// ---------------- weight transform: [K][N] fp32 -> [N][K] bf16 hi/lo ----------------
__global__ __launch_bounds__(256)
void transform_w_kernel(const float* __restrict__ sw, const float* __restrict__ ew,
                        __nv_bfloat16* __restrict__ ohi, __nv_bfloat16* __restrict__ olo,
                        int K, int N) {
    __shared__ float t[64][65];
    int g = blockIdx.z;
    const float* W = (g == 0) ? sw : (ew + (size_t)(g - 1) * K * N);
    int k0 = blockIdx.y * 64, nn0 = blockIdx.x * 64;
    int tid = threadIdx.x;
#pragma unroll
    for (int j = 0; j < 4; j++) {
        int row = (tid >> 4) + j * 16, col = (tid & 15) * 4;
        float4 v = *(const float4*)(W + (size_t)(k0 + row) * N + nn0 + col);
        t[row][col] = v.x; t[row][col + 1] = v.y; t[row][col + 2] = v.z; t[row][col + 3] = v.w;
    }
    __syncthreads();
    int n = tid >> 2, ks = (tid & 3) * 16;
    union { __nv_bfloat16 h[16]; uint4 q[2]; } hi, lo;
#pragma unroll
    for (int j = 0; j < 16; j++) {
        float v = t[ks + j][n];
        __nv_bfloat16 hb = __float2bfloat16(v);
        hi.h[j] = hb;
        lo.h[j] = __float2bfloat16(v - __bfloat162float(hb));
    }
    size_t o = ((size_t)g * N + nn0 + n) * K + k0 + ks;
    *(uint4*)(ohi + o) = hi.q[0]; *(uint4*)(ohi + o + 8) = hi.q[1];
    *(uint4*)(olo + o) = lo.q[0]; *(uint4*)(olo + o + 8) = lo.q[1];
}

// ---------------- GEMM compute core ----------------
// A: 128 rows x 64 cols (hi at +0, lo at +16384); B: 256 rows x 64 cols (hi at +32768, lo at +65536)
// swizzled smem row: 128B; addr = row*128 + ((chunk ^ (row&7))<<4)
// warps: warp_m in 0..3 (32-row slice), warp_n in 0..1 (128-col slice); acc[2][16][4]
#define GEMM_COMPUTE(stbase)                                                          \
    {                                                                                 \
        uint32_t aB = (stbase) + warp_m * (32 * 128);                                 \
        uint32_t bB = (stbase) + 32768 + warp_n * (128 * 128);                        \
        _Pragma("unroll")                                                             \
        for (int kk = 0; kk < 4; kk++) {                                              \
            uint4 Ah[2], Al[2];                                                       \
            _Pragma("unroll")                                                         \
            for (int mi = 0; mi < 2; mi++) {                                          \
                int rl = mi * 16 + (lane & 15);                                       \
                int ck = kk * 2 + (lane >> 4);                                        \
                uint32_t off = rl * 128 + ((ck ^ (rl & 7)) << 4);                     \
                Ah[mi] = ldm4(aB + off);                                              \
                Al[mi] = ldm4(aB + off + 16384);                                      \
            }                                                                         \
            _Pragma("unroll")                                                         \
            for (int p = 0; p < 8; p++) {                                             \
                int nl = p * 16 + ((lane >> 4) << 3) + (lane & 7);                    \
                int ck = kk * 2 + ((lane >> 3) & 1);                                  \
                uint32_t off = nl * 128 + ((ck ^ (nl & 7)) << 4);                     \
                uint4 Bh = ldm4(bB + off);                                            \
                uint4 Bl = ldm4(bB + off + 32768);                                    \
                _Pragma("unroll")                                                     \
                for (int mi = 0; mi < 2; mi++) {                                      \
                    mma16816(acc[mi][2 * p],     Ah[mi], Bh.x, Bh.y);                 \
                    mma16816(acc[mi][2 * p + 1], Ah[mi], Bh.z, Bh.w);                 \
                    mma16816(acc[mi][2 * p],     Ah[mi], Bl.x, Bl.y);                 \
                    mma16816(acc[mi][2 * p + 1], Ah[mi], Bl.z, Bl.w);                 \
                    mma16816(acc[mi][2 * p],     Al[mi], Bh.x, Bh.y);                 \
                    mma16816(acc[mi][2 * p + 1], Al[mi], Bh.z, Bh.w);                 \
                }                                                                     \
            }                                                                         \
        }                                                                             \
    }

// ---------------- GEMM1: h = gelu(gather(x) @ W1_g + b1_g), tile 128x256 ----------------
__global__ __launch_bounds__(256, 1)
void gemm1_mma(const float* __restrict__ sb1, const float* __restrict__ eb1) {
    extern __shared__ char sm[];
    __shared__ int s_tok[128];
    __shared__ float s_bias[256];
    uint32_t smb = smem_u32(sm);
    int tid = threadIdx.x, lane = tid & 31, wid = tid >> 5;
    int warp_m = wid & 3, warp_n = wid >> 2;
    int rb = blockIdx.y, nb = blockIdx.x;
    int row0 = rb * 128, n0 = nb * 256;
    if (row0 >= d_est[N_EXP]) return;
    int g = 0;
    if (row0 >= EXP_BASE) {
        int e = 0;
#pragma unroll
        for (int i = 1; i < N_EXP; i++) if (row0 >= d_est[i]) e = i;
        g = e + 1;
    }
    const float* bias = (g == 0) ? sb1 : (eb1 + (size_t)(g - 1) * D_FF);
    if (tid < 128) s_tok[tid] = d_row_tok[row0 + tid];
    s_bias[tid] = bias[n0 + tid];
    s_bias[tid + 256 - 256] = s_bias[tid];  // no-op keep
    s_bias[tid] = bias[n0 + tid];
    if (tid < 0) {}
    { int t2 = tid + 256; if (t2 < 256) {} }
    s_bias[tid] = bias[n0 + tid];
    // second half of bias
    if (tid < 256) {}
    __syncthreads();
    if (tid < 128) {}  // (bias fully loaded below)
    s_bias[tid] = bias[n0 + tid];
    __syncthreads();

    const __nv_bfloat16* whi = d_w1hi + ((size_t)g * D_FF + n0) * D_MODEL;
    const __nv_bfloat16* wlo = d_w1lo + ((size_t)g * D_FF + n0) * D_MODEL;

    float acc[2][16][4];
#pragma unroll
    for (int a = 0; a < 2; a++)
#pragma unroll
        for (int b = 0; b < 16; b++)
#pragma unroll
            for (int c = 0; c < 4; c++) acc[a][b][c] = 0.0f;

    auto load_stage = [&](int i, int st) {
        uint32_t bb = smb + st * STAGE_SZ;
#pragma unroll
        for (int j = 0; j < 4; j++) {
            int ch = tid * 4 + j; int r = ch >> 3, c = ch & 7;
            int tok = s_tok[r];
            int sz = (tok >= 0) ? 16 : 0;
            size_t so = (size_t)(tok < 0 ? 0 : tok) * D_MODEL + i * 64 + c * 8;
            uint32_t dsw = bb + r * 128 + ((c ^ (r & 7)) << 4);
            cpa(dsw, d_xhi + so, sz);
            cpa(dsw + 16384, d_xlo + so, sz);
        }
#pragma unroll
        for (int j = 0; j < 8; j++) {
            int ch = tid * 8 + j; int r = ch >> 3, c = ch & 7;
            size_t so = (size_t)r * D_MODEL + i * 64 + c * 8;
            uint32_t dsw = bb + 32768 + r * 128 + ((c ^ (r & 7)) << 4);
            cpa(dsw, whi + so, 16);
            cpa(dsw + 32768, wlo + so, 16);
        }
        CP_COMMIT();
    };

    const int NCH = D_MODEL / 64;  // 16
    load_stage(0, 0);
    for (int i = 0; i < NCH; i++) {
        int st = i & 1;
        CP_WAIT0();
        __syncthreads();
        if (i + 1 < NCH) load_stage(i + 1, st ^ 1);
        GEMM_COMPUTE(smb + st * STAGE_SZ);
    }

    // epilogue: bias + gelu + bf16 hi/lo split -> d_hhi/d_hlo
#pragma unroll
    for (int mi = 0; mi < 2; mi++)
#pragma unroll
        for (int nj = 0; nj < 16; nj++) {
            int cl = warp_n * 128 + nj * 8 + ((lane & 3) << 1);
            float b0v = s_bias[cl], b1v = s_bias[cl + 1];
            int rw0 = row0 + warp_m * 32 + mi * 16 + (lane >> 2);
#pragma unroll
            for (int hh = 0; hh < 2; hh++) {
                float v0 = gelu_exact(acc[mi][nj][hh * 2 + 0] + b0v);
                float v1 = gelu_exact(acc[mi][nj][hh * 2 + 1] + b1v);
                union { __nv_bfloat16 h[2]; uint32_t u; } hi, lo;
                hi.h[0] = __float2bfloat16(v0);
                lo.h[0] = __float2bfloat16(v0 - __bfloat162float(hi.h[0]));
                hi.h[1] = __float2bfloat16(v1);
                lo.h[1] = __float2bfloat16(v1 - __bfloat162float(hi.h[1]));
                size_t o = (size_t)(rw0 + hh * 8) * D_FF + n0 + cl;
                *(uint32_t*)(d_hhi + o) = hi.u;
                *(uint32_t*)(d_hlo + o) = lo.u;
            }
        }
}

// ---------------- GEMM2: y = h @ W2_g + b2_g, tile 128x256 ----------------
__global__ __launch_bounds__(256, 1)
void gemm2_mma(const float* __restrict__ sb2, const float* __restrict__ eb2) {
    extern __shared__ char sm[];
    __shared__ float s_bias[256];
    uint32_t smb = smem_u32(sm);
    int tid = threadIdx.x, lane = tid & 31, wid = tid >> 5;
    int warp_m = wid & 3, warp_n = wid >> 2;
    int rb = blockIdx.y, nb = blockIdx.x;
    int row0 = rb * 128, n0 = nb * 256;
    if (row0 >= d_est[N_EXP]) return;
    int g = 0;
    if (row0 >= EXP_BASE) {
        int e = 0;
#pragma unroll
        for (int i = 1; i < N_EXP; i++) if (row0 >= d_est[i]) e = i;
        g = e + 1;
    }
    const float* bias = (g == 0) ? sb2 : (eb2 + (size_t)(g - 1) * D_MODEL);
    s_bias[tid] = bias[n0 + tid];
    __syncthreads();

    const __nv_bfloat16* whi = d_w2hi + ((size_t)g * D_MODEL + n0) * D_FF;
    const __nv_bfloat16* wlo = d_w2lo + ((size_t)g * D_MODEL + n0) * D_FF;

    float acc[2][16][4];
#pragma unroll
    for (int a = 0; a < 2; a++)
#pragma unroll
        for (int b = 0; b < 16; b++)
#pragma unroll
            for (int c = 0; c < 4; c++) acc[a][b][c] = 0.0f;

    auto load_stage = [&](int i, int st) {
        uint32_t bb = smb + st * STAGE_SZ;
#pragma unroll
        for (int j = 0; j < 4; j++) {
            int ch = tid * 4 + j; int r = ch >> 3, c = ch & 7;
            size_t so = (size_t)(row0 + r) * D_FF + i * 64 + c * 8;
            uint32_t dsw = bb + r * 128 + ((c ^ (r & 7)) << 4);
            cpa(dsw, d_hhi + so, 16);
            cpa(dsw + 16384, d_hlo + so, 16);
        }
#pragma unroll
        for (int j = 0; j < 8; j++) {
            int ch = tid * 8 + j; int r = ch >> 3, c = ch & 7;
            size_t so = (size_t)r * D_FF + i * 64 + c * 8;
            uint32_t dsw = bb + 32768 + r * 128 + ((c ^ (r & 7)) << 4);
            cpa(dsw, whi + so, 16);
            cpa(dsw + 32768, wlo + so, 16);
        }
        CP_COMMIT();
    };

    const int NCH = D_FF / 64;  // 64
    load_stage(0, 0);
    for (int i = 0; i < NCH; i++) {
        int st = i & 1;
        CP_WAIT0();
        __syncthreads();
        if (i + 1 < NCH) load_stage(i + 1, st ^ 1);
        GEMM_COMPUTE(smb + st * STAGE_SZ);
    }

#pragma unroll
    for (int mi = 0; mi < 2; mi++)
#pragma unroll
        for (int nj = 0; nj < 16; nj++) {
            int cl = warp_n * 128 + nj * 8 + ((lane & 3) << 1);
            float b0v = s_bias[cl], b1v = s_bias[cl + 1];
            int rw0 = row0 + warp_m * 32 + mi * 16 + (lane >> 2);
#pragma unroll
            for (int hh = 0; hh < 2; hh++) {
                float2 v;
                v.x = acc[mi][nj][hh * 2 + 0] + b0v;
                v.y = acc[mi][nj][hh * 2 + 1] + b1v;
                *(float2*)(d_y + (size_t)(rw0 + hh * 8) * D_MODEL + n0 + cl) = v;
            }
        }
}

// ---------------- combine ----------------
__global__ void combine_kernel(float* __restrict__ out) {
    int t = blockIdx.x;
    int i = threadIdx.x;
    int s0 = d_slot0[t], s1 = d_slot1[t];
    float w0 = d_w0[t], w1 = d_w1v[t];
    float4 a  = *(const float4*)(d_y + (size_t)t  * D_MODEL + i * 4);
    float4 p0 = *(const float4*)(d_y + (size_t)s0 * D_MODEL + i * 4);
    float4 p1 = *(const float4*)(d_y + (size_t)s1 * D_MODEL + i * 4);
    float4 r;
    r.x = a.x + w0 * p0.x + w1 * p1.x;
    r.y = a.y + w0 * p0.y + w1 * p1.y;
    r.z = a.z + w0 * p0.z + w1 * p1.z;
    r.w = a.w + w0 * p0.w + w1 * p1.w;
    *(float4*)(out + (size_t)t * D_MODEL + i * 4) = r;
}

// ---------------- launch ----------------
extern "C" void kernel_launch(void* const* d_in, const int* in_sizes, int n_in,
                              void* d_out, int out_size) {
    const float* x   = (const float*)d_in[0];
    const float* sw1 = (const float*)d_in[1];
    const float* sb1 = (const float*)d_in[2];
    const float* sw2 = (const float*)d_in[3];
    const float* sb2 = (const float*)d_in[4];
    const float* rw  = (const float*)d_in[5];
    const float* rb  = (const float*)d_in[6];
    const float* ew1 = (const float*)d_in[7];
    const float* eb1 = (const float*)d_in[8];
    const float* ew2 = (const float*)d_in[9];
    const float* eb2 = (const float*)d_in[10];
    float* out = (float*)d_out;

    static bool attr_set = false;
    if (!attr_set) {
        cudaFuncSetAttribute(gemm1_mma, cudaFuncAttributeMaxDynamicSharedMemorySize, GEMM_SMEM);
        cudaFuncSetAttribute(gemm2_mma, cudaFuncAttributeMaxDynamicSharedMemorySize, GEMM_SMEM);
        attr_set = true;
    }

    init_kernel<<<(MAX_ROWS + 255) / 256, 256>>>();
    router_kernel<<<(T_TOK * 32 + 255) / 256, 256>>>(x, rw, rb);
    offsets_kernel<<<1, 32>>>();
    scatter_kernel<<<(T_TOK + 255) / 256, 256>>>();

    split_x_kernel<<<(T_TOK * D_MODEL) / (256 * 4), 256>>>(x);

    __nv_bfloat16 *w1hi, *w1lo, *w2hi, *w2lo;
    cudaGetSymbolAddress((void**)&w1hi, d_w1hi);
    cudaGetSymbolAddress((void**)&w1lo, d_w1lo);
    cudaGetSymbolAddress((void**)&w2hi, d_w2hi);
    cudaGetSymbolAddress((void**)&w2lo, d_w2lo);
    transform_w_kernel<<<dim3(D_FF / 64, D_MODEL / 64, 9), 256>>>(sw1, ew1, w1hi, w1lo, D_MODEL, D_FF);
    transform_w_kernel<<<dim3(D_MODEL / 64, D_FF / 64, 9), 256>>>(sw2, ew2, w2hi, w2lo, D_FF, D_MODEL);

    gemm1_mma<<<dim3(D_FF / 256, NRB), 256, GEMM_SMEM>>>(sb1, eb1);
    gemm2_mma<<<dim3(D_MODEL / 256, NRB), 256, GEMM_SMEM>>>(sb2, eb2);

    combine_kernel<<<T_TOK, 256>>>(out);
}

// round 13
// speedup vs baseline: 1.1301x; 1.1301x over previous
#include <cuda_runtime.h>
#include <cuda_bf16.h>
#include <math.h>
#include <stdint.h>

#define T_TOK   8192
#define D_MODEL 1024
#define D_FF    4096
#define N_EXP   8
#define EXP_BASE 8192
#define MAX_ROWS 25600
#define NRB (MAX_ROWS / 128)   // 200

// ---------------- device scratch (static) ----------------
__device__ __align__(128) __nv_bfloat16 d_xhi[(size_t)T_TOK * D_MODEL];
__device__ __align__(128) __nv_bfloat16 d_xlo[(size_t)T_TOK * D_MODEL];
__device__ __align__(128) __nv_bfloat16 d_w1hi[(size_t)9 * D_FF * D_MODEL];   // [g][N=4096][K=1024]
__device__ __align__(128) __nv_bfloat16 d_w1lo[(size_t)9 * D_FF * D_MODEL];
__device__ __align__(128) __nv_bfloat16 d_w2hi[(size_t)9 * D_MODEL * D_FF];   // [g][N=1024][K=4096]
__device__ __align__(128) __nv_bfloat16 d_w2lo[(size_t)9 * D_MODEL * D_FF];
__device__ __align__(128) __nv_bfloat16 d_hhi[(size_t)MAX_ROWS * D_FF];
__device__ __align__(128) __nv_bfloat16 d_hlo[(size_t)MAX_ROWS * D_FF];
__device__ __align__(128) float d_y[(size_t)MAX_ROWS * D_MODEL];
__device__ int   d_row_tok[MAX_ROWS];
__device__ int   d_e0[T_TOK], d_e1[T_TOK];
__device__ float d_w0[T_TOK], d_w1v[T_TOK];
__device__ int   d_slot0[T_TOK], d_slot1[T_TOK];
__device__ int   d_counts[N_EXP];
__device__ int   d_fill[N_EXP];
__device__ int   d_est[N_EXP + 1];

// ---------------- helpers ----------------
__device__ __forceinline__ uint32_t smem_u32(const void* p) {
    uint32_t a;
    asm("{ .reg .u64 t; cvta.to.shared.u64 t, %1; cvt.u32.u64 %0, t; }" : "=r"(a) : "l"(p));
    return a;
}
__device__ __forceinline__ void cpa(uint32_t d, const void* s, int sz) {
    asm volatile("cp.async.cg.shared.global [%0], [%1], 16, %2;" :: "r"(d), "l"(s), "r"(sz) : "memory");
}
#define CP_COMMIT() asm volatile("cp.async.commit_group;" ::: "memory")
#define CP_WAIT1()  asm volatile("cp.async.wait_group 1;" ::: "memory")
#define CP_WAIT0()  asm volatile("cp.async.wait_group 0;" ::: "memory")

__device__ __forceinline__ uint4 ldm4(uint32_t a) {
    uint4 r;
    asm volatile("ldmatrix.sync.aligned.m8n8.x4.shared.b16 {%0,%1,%2,%3}, [%4];"
                 : "=r"(r.x), "=r"(r.y), "=r"(r.z), "=r"(r.w) : "r"(a));
    return r;
}
__device__ __forceinline__ void mma16816(float* c, const uint4& a, uint32_t b0, uint32_t b1) {
    asm volatile(
        "mma.sync.aligned.m16n8k16.row.col.f32.bf16.bf16.f32 "
        "{%0,%1,%2,%3},{%4,%5,%6,%7},{%8,%9},{%0,%1,%2,%3};"
        : "+f"(c[0]), "+f"(c[1]), "+f"(c[2]), "+f"(c[3])
        : "r"(a.x), "r"(a.y), "r"(a.z), "r"(a.w), "r"(b0), "r"(b1));
}
__device__ __forceinline__ float gelu_exact(float v) {
    return 0.5f * v * (1.0f + erff(v * 0.70710678118654752440f));
}

// smem stage layout: A_hi[0,16K) A_lo[16K,32K) B_hi[32K,48K) B_lo[48K,64K); 3 stages
#define STAGE_SZ 65536
#define GEMM_SMEM (3 * STAGE_SZ)   // 192 KB

// ---------------- init / router / offsets / scatter ----------------
__global__ void init_kernel() {
    int i = blockIdx.x * blockDim.x + threadIdx.x;
    if (i < N_EXP) { d_counts[i] = 0; d_fill[i] = 0; }
    if (i < MAX_ROWS) d_row_tok[i] = (i < T_TOK) ? i : -1;
}

__global__ void router_kernel(const float* __restrict__ x,
                              const float* __restrict__ rw,
                              const float* __restrict__ rb) {
    int gid = blockIdx.x * blockDim.x + threadIdx.x;
    int t = gid >> 5, lane = gid & 31;
    if (t >= T_TOK) return;
    const float* xr = x + (size_t)t * D_MODEL;
    float acc[N_EXP];
#pragma unroll
    for (int e = 0; e < N_EXP; e++) acc[e] = 0.0f;
    for (int k = lane; k < D_MODEL; k += 32) {
        float xv = xr[k];
        const float4* w4 = (const float4*)(rw + (size_t)k * N_EXP);
        float4 wa = w4[0], wb = w4[1];
        acc[0] += xv * wa.x; acc[1] += xv * wa.y; acc[2] += xv * wa.z; acc[3] += xv * wa.w;
        acc[4] += xv * wb.x; acc[5] += xv * wb.y; acc[6] += xv * wb.z; acc[7] += xv * wb.w;
    }
#pragma unroll
    for (int off = 16; off > 0; off >>= 1)
#pragma unroll
        for (int e = 0; e < N_EXP; e++) acc[e] += __shfl_xor_sync(0xFFFFFFFFu, acc[e], off);
    if (lane == 0) {
        float l[N_EXP], m = -1e30f;
#pragma unroll
        for (int e = 0; e < N_EXP; e++) { l[e] = acc[e] + rb[e]; m = fmaxf(m, l[e]); }
        float p[N_EXP], s = 0.0f;
#pragma unroll
        for (int e = 0; e < N_EXP; e++) { p[e] = __expf(l[e] - m); s += p[e]; }
        float inv = 1.0f / s;
#pragma unroll
        for (int e = 0; e < N_EXP; e++) p[e] *= inv;
        int i0 = 0; float p0 = p[0];
#pragma unroll
        for (int e = 1; e < N_EXP; e++) if (p[e] > p0) { p0 = p[e]; i0 = e; }
        int i1 = -1; float p1 = -1e30f;
#pragma unroll
        for (int e = 0; e < N_EXP; e++) { if (e == i0) continue; if (p[e] > p1) { p1 = p[e]; i1 = e; } }
        float denom = p0 + p1 + 1e-9f;
        d_e0[t] = i0; d_e1[t] = i1;
        d_w0[t] = p0 / denom; d_w1v[t] = p1 / denom;
        atomicAdd(&d_counts[i0], 1);
        atomicAdd(&d_counts[i1], 1);
    }
}

__global__ void offsets_kernel() {
    if (threadIdx.x == 0 && blockIdx.x == 0) {
        int run = EXP_BASE;
#pragma unroll
        for (int e = 0; e < N_EXP; e++) { d_est[e] = run; run += (d_counts[e] + 127) & ~127; }
        d_est[N_EXP] = run;
    }
}

__global__ void scatter_kernel() {
    int t = blockIdx.x * blockDim.x + threadIdx.x;
    if (t >= T_TOK) return;
    int e0 = d_e0[t];
    int r0 = d_est[e0] + atomicAdd(&d_fill[e0], 1);
    d_row_tok[r0] = t; d_slot0[t] = r0;
    int e1 = d_e1[t];
    int r1 = d_est[e1] + atomicAdd(&d_fill[e1], 1);
    d_row_tok[r1] = t; d_slot1[t] = r1;
}

// ---------------- x split: fp32 -> bf16 hi/lo ----------------
__global__ void split_x_kernel(const float* __restrict__ x) {
    size_t i = ((size_t)blockIdx.x * blockDim.x + threadIdx.x) * 4;
    float4 v = *(const float4*)(x + i);
    union { __nv_bfloat16 h[4]; uint2 u; } hi, lo;
    float f[4] = { v.x, v.y, v.z, v.w };
#pragma unroll
    for (int j = 0; j < 4; j++) {
        __nv_bfloat16 hb = __float2bfloat16(f[j]);
        hi.h[j] = hb;
        lo.h[j] = __float2bfloat16(f[j] - __bfloat162float(hb));
    }
    *(uint2*)(d_xhi + i) = hi.u;
    *(uint2*)(d_xlo + i) = lo.u;
}

// ---------------- weight transform: [K][N] fp32 -> [N][K] bf16 hi/lo ----------------
__global__ __launch_bounds__(256)
void transform_w_kernel(const float* __restrict__ sw, const float* __restrict__ ew,
                        __nv_bfloat16* __restrict__ ohi, __nv_bfloat16* __restrict__ olo,
                        int K, int N) {
    __shared__ float t[64][65];
    int g = blockIdx.z;
    const float* W = (g == 0) ? sw : (ew + (size_t)(g - 1) * K * N);
    int k0 = blockIdx.y * 64, nn0 = blockIdx.x * 64;
    int tid = threadIdx.x;
#pragma unroll
    for (int j = 0; j < 4; j++) {
        int row = (tid >> 4) + j * 16, col = (tid & 15) * 4;
        float4 v = *(const float4*)(W + (size_t)(k0 + row) * N + nn0 + col);
        t[row][col] = v.x; t[row][col + 1] = v.y; t[row][col + 2] = v.z; t[row][col + 3] = v.w;
    }
    __syncthreads();
    int n = tid >> 2, ks = (tid & 3) * 16;
    union { __nv_bfloat16 h[16]; uint4 q[2]; } hi, lo;
#pragma unroll
    for (int j = 0; j < 16; j++) {
        float v = t[ks + j][n];
        __nv_bfloat16 hb = __float2bfloat16(v);
        hi.h[j] = hb;
        lo.h[j] = __float2bfloat16(v - __bfloat162float(hb));
    }
    size_t o = ((size_t)g * N + nn0 + n) * K + k0 + ks;
    *(uint4*)(ohi + o) = hi.q[0]; *(uint4*)(ohi + o + 8) = hi.q[1];
    *(uint4*)(olo + o) = lo.q[0]; *(uint4*)(olo + o + 8) = lo.q[1];
}

// ---------------- GEMM compute core (128x128 tile, warp 32x64) ----------------
// swizzled smem row: 128B (64 bf16); addr = row*128 + ((chunk ^ (row&7))<<4)
#define GEMM_COMPUTE(stbase)                                                          \
    {                                                                                 \
        uint32_t aB = (stbase) + warp_m * (32 * 128);                                 \
        uint32_t bB = (stbase) + 32768 + warp_n * (64 * 128);                         \
        _Pragma("unroll")                                                             \
        for (int kk = 0; kk < 4; kk++) {                                              \
            uint4 Ah[2], Al[2], Bh[4], Bl[4];                                         \
            _Pragma("unroll")                                                         \
            for (int mi = 0; mi < 2; mi++) {                                          \
                int rl = mi * 16 + (lane & 15);                                       \
                int ck = kk * 2 + (lane >> 4);                                        \
                uint32_t off = rl * 128 + ((ck ^ (rl & 7)) << 4);                     \
                Ah[mi] = ldm4(aB + off);                                              \
                Al[mi] = ldm4(aB + off + 16384);                                      \
            }                                                                         \
            _Pragma("unroll")                                                         \
            for (int p = 0; p < 4; p++) {                                             \
                int nl = p * 16 + ((lane >> 4) << 3) + (lane & 7);                    \
                int ck = kk * 2 + ((lane >> 3) & 1);                                  \
                uint32_t off = nl * 128 + ((ck ^ (nl & 7)) << 4);                     \
                Bh[p] = ldm4(bB + off);                                               \
                Bl[p] = ldm4(bB + off + 16384);                                       \
            }                                                                         \
            _Pragma("unroll")                                                         \
            for (int mi = 0; mi < 2; mi++) {                                          \
                _Pragma("unroll")                                                     \
                for (int p = 0; p < 4; p++) {                                         \
                    mma16816(acc[mi][2 * p],     Ah[mi], Bh[p].x, Bh[p].y);           \
                    mma16816(acc[mi][2 * p + 1], Ah[mi], Bh[p].z, Bh[p].w);           \
                    mma16816(acc[mi][2 * p],     Ah[mi], Bl[p].x, Bl[p].y);           \
                    mma16816(acc[mi][2 * p + 1], Ah[mi], Bl[p].z, Bl[p].w);           \
                    mma16816(acc[mi][2 * p],     Al[mi], Bh[p].x, Bh[p].y);           \
                    mma16816(acc[mi][2 * p + 1], Al[mi], Bh[p].z, Bh[p].w);           \
                }                                                                     \
            }                                                                         \
        }                                                                             \
    }

// ---------------- GEMM1: h = gelu(gather(x) @ W1_g + b1_g) ----------------
__global__ __launch_bounds__(256, 1)
void gemm1_mma(const float* __restrict__ sb1, const float* __restrict__ eb1) {
    extern __shared__ char sm[];
    __shared__ int s_tok[128];
    __shared__ float s_bias[128];
    uint32_t smb = smem_u32(sm);
    int tid = threadIdx.x, lane = tid & 31, wid = tid >> 5;
    int warp_m = wid & 3, warp_n = wid >> 2;
    int rb = blockIdx.y, nb = blockIdx.x;
    int row0 = rb * 128, n0 = nb * 128;
    if (row0 >= d_est[N_EXP]) return;
    int g = 0;
    if (row0 >= EXP_BASE) {
        int e = 0;
#pragma unroll
        for (int i = 1; i < N_EXP; i++) if (row0 >= d_est[i]) e = i;
        g = e + 1;
    }
    const float* bias = (g == 0) ? sb1 : (eb1 + (size_t)(g - 1) * D_FF);
    if (tid < 128) { s_tok[tid] = d_row_tok[row0 + tid]; s_bias[tid] = bias[n0 + tid]; }
    __syncthreads();

    const __nv_bfloat16* whi = d_w1hi + ((size_t)g * D_FF + n0) * D_MODEL;
    const __nv_bfloat16* wlo = d_w1lo + ((size_t)g * D_FF + n0) * D_MODEL;

    float acc[2][8][4];
#pragma unroll
    for (int a = 0; a < 2; a++)
#pragma unroll
        for (int b = 0; b < 8; b++)
#pragma unroll
            for (int c = 0; c < 4; c++) acc[a][b][c] = 0.0f;

    auto load_stage = [&](int i, int st) {
        uint32_t bb = smb + st * STAGE_SZ;
#pragma unroll
        for (int j = 0; j < 4; j++) {
            int ch = tid * 4 + j; int r = ch >> 3, c = ch & 7;
            int tok = s_tok[r];
            int sz = (tok >= 0) ? 16 : 0;
            size_t so = (size_t)(tok < 0 ? 0 : tok) * D_MODEL + i * 64 + c * 8;
            uint32_t dsw = bb + r * 128 + ((c ^ (r & 7)) << 4);
            cpa(dsw, d_xhi + so, sz);
            cpa(dsw + 16384, d_xlo + so, sz);
        }
#pragma unroll
        for (int j = 0; j < 4; j++) {
            int ch = tid * 4 + j; int r = ch >> 3, c = ch & 7;
            size_t so = (size_t)r * D_MODEL + i * 64 + c * 8;
            uint32_t dsw = bb + 32768 + r * 128 + ((c ^ (r & 7)) << 4);
            cpa(dsw, whi + so, 16);
            cpa(dsw + 16384, wlo + so, 16);
        }
        CP_COMMIT();
    };

    const int NCH = D_MODEL / 64;  // 16
    load_stage(0, 0);
    load_stage(1, 1);
    for (int i = 0; i < NCH; i++) {
        int st = i % 3;
        if (i + 1 < NCH) CP_WAIT1(); else CP_WAIT0();
        __syncthreads();
        if (i + 2 < NCH) load_stage(i + 2, (i + 2) % 3);
        GEMM_COMPUTE(smb + st * STAGE_SZ);
    }

    // epilogue: bias + gelu + bf16 hi/lo split -> d_hhi/d_hlo
#pragma unroll
    for (int mi = 0; mi < 2; mi++)
#pragma unroll
        for (int nj = 0; nj < 8; nj++) {
            int cl = warp_n * 64 + nj * 8 + ((lane & 3) << 1);
            float b0v = s_bias[cl], b1v = s_bias[cl + 1];
            int rw0 = row0 + warp_m * 32 + mi * 16 + (lane >> 2);
#pragma unroll
            for (int hh = 0; hh < 2; hh++) {
                float v0 = gelu_exact(acc[mi][nj][hh * 2 + 0] + b0v);
                float v1 = gelu_exact(acc[mi][nj][hh * 2 + 1] + b1v);
                union { __nv_bfloat16 h[2]; uint32_t u; } hi, lo;
                hi.h[0] = __float2bfloat16(v0);
                lo.h[0] = __float2bfloat16(v0 - __bfloat162float(hi.h[0]));
                hi.h[1] = __float2bfloat16(v1);
                lo.h[1] = __float2bfloat16(v1 - __bfloat162float(hi.h[1]));
                size_t o = (size_t)(rw0 + hh * 8) * D_FF + n0 + cl;
                *(uint32_t*)(d_hhi + o) = hi.u;
                *(uint32_t*)(d_hlo + o) = lo.u;
            }
        }
}

// ---------------- GEMM2: y = h @ W2_g + b2_g ----------------
__global__ __launch_bounds__(256, 1)
void gemm2_mma(const float* __restrict__ sb2, const float* __restrict__ eb2) {
    extern __shared__ char sm[];
    __shared__ float s_bias[128];
    uint32_t smb = smem_u32(sm);
    int tid = threadIdx.x, lane = tid & 31, wid = tid >> 5;
    int warp_m = wid & 3, warp_n = wid >> 2;
    int rb = blockIdx.y, nb = blockIdx.x;
    int row0 = rb * 128, n0 = nb * 128;
    if (row0 >= d_est[N_EXP]) return;
    int g = 0;
    if (row0 >= EXP_BASE) {
        int e = 0;
#pragma unroll
        for (int i = 1; i < N_EXP; i++) if (row0 >= d_est[i]) e = i;
        g = e + 1;
    }
    const float* bias = (g == 0) ? sb2 : (eb2 + (size_t)(g - 1) * D_MODEL);
    if (tid < 128) s_bias[tid] = bias[n0 + tid];
    __syncthreads();

    const __nv_bfloat16* whi = d_w2hi + ((size_t)g * D_MODEL + n0) * D_FF;
    const __nv_bfloat16* wlo = d_w2lo + ((size_t)g * D_MODEL + n0) * D_FF;

    float acc[2][8][4];
#pragma unroll
    for (int a = 0; a < 2; a++)
#pragma unroll
        for (int b = 0; b < 8; b++)
#pragma unroll
            for (int c = 0; c < 4; c++) acc[a][b][c] = 0.0f;

    auto load_stage = [&](int i, int st) {
        uint32_t bb = smb + st * STAGE_SZ;
#pragma unroll
        for (int j = 0; j < 4; j++) {
            int ch = tid * 4 + j; int r = ch >> 3, c = ch & 7;
            size_t so = (size_t)(row0 + r) * D_FF + i * 64 + c * 8;
            uint32_t dsw = bb + r * 128 + ((c ^ (r & 7)) << 4);
            cpa(dsw, d_hhi + so, 16);
            cpa(dsw + 16384, d_hlo + so, 16);
        }
#pragma unroll
        for (int j = 0; j < 4; j++) {
            int ch = tid * 4 + j; int r = ch >> 3, c = ch & 7;
            size_t so = (size_t)r * D_FF + i * 64 + c * 8;
            uint32_t dsw = bb + 32768 + r * 128 + ((c ^ (r & 7)) << 4);
            cpa(dsw, whi + so, 16);
            cpa(dsw + 16384, wlo + so, 16);
        }
        CP_COMMIT();
    };

    const int NCH = D_FF / 64;  // 64
    load_stage(0, 0);
    load_stage(1, 1);
    for (int i = 0; i < NCH; i++) {
        int st = i % 3;
        if (i + 1 < NCH) CP_WAIT1(); else CP_WAIT0();
        __syncthreads();
        if (i + 2 < NCH) load_stage(i + 2, (i + 2) % 3);
        GEMM_COMPUTE(smb + st * STAGE_SZ);
    }

#pragma unroll
    for (int mi = 0; mi < 2; mi++)
#pragma unroll
        for (int nj = 0; nj < 8; nj++) {
            int cl = warp_n * 64 + nj * 8 + ((lane & 3) << 1);
            float b0v = s_bias[cl], b1v = s_bias[cl + 1];
            int rw0 = row0 + warp_m * 32 + mi * 16 + (lane >> 2);
#pragma unroll
            for (int hh = 0; hh < 2; hh++) {
                float2 v;
                v.x = acc[mi][nj][hh * 2 + 0] + b0v;
                v.y = acc[mi][nj][hh * 2 + 1] + b1v;
                *(float2*)(d_y + (size_t)(rw0 + hh * 8) * D_MODEL + n0 + cl) = v;
            }
        }
}

// ---------------- combine ----------------
__global__ void combine_kernel(float* __restrict__ out) {
    int t = blockIdx.x;
    int i = threadIdx.x;
    int s0 = d_slot0[t], s1 = d_slot1[t];
    float w0 = d_w0[t], w1 = d_w1v[t];
    float4 a  = *(const float4*)(d_y + (size_t)t  * D_MODEL + i * 4);
    float4 p0 = *(const float4*)(d_y + (size_t)s0 * D_MODEL + i * 4);
    float4 p1 = *(const float4*)(d_y + (size_t)s1 * D_MODEL + i * 4);
    float4 r;
    r.x = a.x + w0 * p0.x + w1 * p1.x;
    r.y = a.y + w0 * p0.y + w1 * p1.y;
    r.z = a.z + w0 * p0.z + w1 * p1.z;
    r.w = a.w + w0 * p0.w + w1 * p1.w;
    *(float4*)(out + (size_t)t * D_MODEL + i * 4) = r;
}

// ---------------- launch ----------------
extern "C" void kernel_launch(void* const* d_in, const int* in_sizes, int n_in,
                              void* d_out, int out_size) {
    const float* x   = (const float*)d_in[0];
    const float* sw1 = (const float*)d_in[1];
    const float* sb1 = (const float*)d_in[2];
    const float* sw2 = (const float*)d_in[3];
    const float* sb2 = (const float*)d_in[4];
    const float* rw  = (const float*)d_in[5];
    const float* rb  = (const float*)d_in[6];
    const float* ew1 = (const float*)d_in[7];
    const float* eb1 = (const float*)d_in[8];
    const float* ew2 = (const float*)d_in[9];
    const float* eb2 = (const float*)d_in[10];
    float* out = (float*)d_out;

    static bool attr_set = false;
    if (!attr_set) {
        cudaFuncSetAttribute(gemm1_mma, cudaFuncAttributeMaxDynamicSharedMemorySize, GEMM_SMEM);
        cudaFuncSetAttribute(gemm2_mma, cudaFuncAttributeMaxDynamicSharedMemorySize, GEMM_SMEM);
        attr_set = true;
    }

    init_kernel<<<(MAX_ROWS + 255) / 256, 256>>>();
    router_kernel<<<(T_TOK * 32 + 255) / 256, 256>>>(x, rw, rb);
    offsets_kernel<<<1, 32>>>();
    scatter_kernel<<<(T_TOK + 255) / 256, 256>>>();

    split_x_kernel<<<(T_TOK * D_MODEL) / (256 * 4), 256>>>(x);

    __nv_bfloat16 *w1hi, *w1lo, *w2hi, *w2lo;
    cudaGetSymbolAddress((void**)&w1hi, d_w1hi);
    cudaGetSymbolAddress((void**)&w1lo, d_w1lo);
    cudaGetSymbolAddress((void**)&w2hi, d_w2hi);
    cudaGetSymbolAddress((void**)&w2lo, d_w2lo);
    transform_w_kernel<<<dim3(D_FF / 64, D_MODEL / 64, 9), 256>>>(sw1, ew1, w1hi, w1lo, D_MODEL, D_FF);
    transform_w_kernel<<<dim3(D_MODEL / 64, D_FF / 64, 9), 256>>>(sw2, ew2, w2hi, w2lo, D_FF, D_MODEL);

    gemm1_mma<<<dim3(D_FF / 128, NRB), 256, GEMM_SMEM>>>(sb1, eb1);
    gemm2_mma<<<dim3(D_MODEL / 128, NRB), 256, GEMM_SMEM>>>(sb2, eb2);

    combine_kernel<<<T_TOK, 256>>>(out);
}